// round 1
// baseline (speedup 1.0000x reference)
#include <cuda_runtime.h>
#include <math.h>

#define B_   256
#define N_   1152
#define C_   10
#define OUT_ 16
#define IN_  8
#define KO_  160            // C_*OUT_
#define BKO_ 40960          // B_*KO_

// u_hat layout: [n][b][ko]  (189 MB)
__device__ float g_uhat[(size_t)N_ * B_ * KO_];
__device__ float g_bij[N_ * C_];
__device__ float g_c[N_ * C_];
__device__ float g_v[B_ * KO_];

// ---------------------------------------------------------------------------
// Kernel 1: u_hat[n][b][ko] = sum_i W[n,ko,i] * x[b,n,i]
// One CTA per n. W[n] (1280 f) transposed into smem -> 40 regs/lane.
// Warp w handles b = w*32..w*32+31; lane l computes ko = l + 32*j, j=0..4.
// ---------------------------------------------------------------------------
__global__ __launch_bounds__(256) void uhat_kernel(const float* __restrict__ x,
                                                   const float* __restrict__ W)
{
    __shared__ float WsT[IN_ * KO_];   // [i][ko], conflict-free compute reads
    __shared__ float xs[B_ * IN_];     // [b][i]
    const int n   = blockIdx.x;
    const int tid = threadIdx.x;

    for (int j = tid; j < KO_ * IN_; j += 256) {
        int ko = j >> 3, i = j & 7;
        WsT[i * KO_ + ko] = W[(size_t)n * (KO_ * IN_) + j];
    }
    for (int j = tid; j < B_ * IN_; j += 256) {
        int b = j >> 3, i = j & 7;
        xs[j] = x[(size_t)b * (N_ * IN_) + n * IN_ + i];
    }
    __syncthreads();

    const int w = tid >> 5, l = tid & 31;
    float wr[5][8];
#pragma unroll
    for (int j = 0; j < 5; j++)
#pragma unroll
        for (int i = 0; i < 8; i++)
            wr[j][i] = WsT[i * KO_ + (l + 32 * j)];

    float* up = g_uhat + (size_t)n * BKO_;
    for (int bb = 0; bb < 32; bb++) {
        const int b = w * 32 + bb;
        float xv[8];
#pragma unroll
        for (int i = 0; i < 8; i++) xv[i] = xs[b * 8 + i];
#pragma unroll
        for (int j = 0; j < 5; j++) {
            float acc = 0.f;
#pragma unroll
            for (int i = 0; i < 8; i++) acc = fmaf(wr[j][i], xv[i], acc);
            up[b * KO_ + l + 32 * j] = acc;   // coalesced per warp per j
        }
    }
}

// ---------------------------------------------------------------------------
// S-pass: s[b,ko] = sum_n c[n,k] * u_hat[n][b][ko]; v = squash(s) elementwise.
// One CTA per b, 160 threads (thread = ko). uniform=1 -> c = 1/C (iter 0).
// out == nullptr -> write g_v, else write to out (final iteration -> d_out).
// ---------------------------------------------------------------------------
__global__ __launch_bounds__(160) void s_kernel(int uniform, float* __restrict__ out)
{
    const int b  = blockIdx.x;
    const int ko = threadIdx.x;
    const int k  = ko >> 4;
    const float* up = g_uhat + (size_t)b * KO_ + ko;

    float acc = 0.f;
    if (uniform) {
        float s = 0.f;
#pragma unroll 8
        for (int n = 0; n < N_; n++)
            s += __ldcs(up + (size_t)n * BKO_);
        acc = 0.1f * s;                       // c = 1/C exactly
    } else {
        const float* cp = g_c + k;
#pragma unroll 8
        for (int n = 0; n < N_; n++)
            acc = fmaf(__ldg(cp + n * C_), __ldcs(up + (size_t)n * BKO_), acc);
    }
    const float v = acc * fabsf(acc) / (1.0f + acc * acc);  // elementwise squash
    float* dst = out ? out : g_v;
    dst[b * KO_ + ko] = v;
}

// ---------------------------------------------------------------------------
// A-pass: a[n,k] = (1/B) sum_{b,o} u_hat[n][b][ko] * v[b][ko];
// b_ij update + softmax over k fused (per-n local). One CTA per n.
// ---------------------------------------------------------------------------
__global__ __launch_bounds__(160) void a_kernel(int first)
{
    const int n  = blockIdx.x;
    const int ko = threadIdx.x;
    const float* up = g_uhat + (size_t)n * BKO_ + ko;
    const float* vp = g_v + ko;

    float t = 0.f;
#pragma unroll 8
    for (int b = 0; b < B_; b++)
        t = fmaf(__ldcs(up + b * KO_), __ldg(vp + b * KO_), t);

    // reduce over o: 16-lane segments within each warp
#pragma unroll
    for (int m = 8; m >= 1; m >>= 1)
        t += __shfl_xor_sync(0xffffffffu, t, m, 16);

    __shared__ float sb[C_];
    if ((ko & 15) == 0) {
        const int k = ko >> 4;
        float bn = t * (1.0f / (float)B_);
        if (!first) bn += g_bij[n * C_ + k];
        g_bij[n * C_ + k] = bn;
        sb[k] = bn;
    }
    __syncthreads();

    if (ko < C_) {
        float mx = -1e30f;
#pragma unroll
        for (int k = 0; k < C_; k++) mx = fmaxf(mx, sb[k]);
        float sum = 0.f;
#pragma unroll
        for (int k = 0; k < C_; k++) sum += expf(sb[k] - mx);
        g_c[n * C_ + ko] = expf(sb[ko] - mx) / sum;
    }
}

// ---------------------------------------------------------------------------
extern "C" void kernel_launch(void* const* d_in, const int* in_sizes, int n_in,
                              void* d_out, int out_size)
{
    const float* x = (const float*)d_in[0];
    const float* W = (const float*)d_in[1];
    // guard against input-order surprises: W has 1,474,560 elems, x 2,359,296
    if (in_sizes[0] == N_ * C_ * OUT_ * IN_) { const float* t = x; x = W; W = t; }
    float* out = (float*)d_out;

    uhat_kernel<<<N_, 256>>>(x, W);

    // iter 0: c uniform -> v0 ; a -> b_ij (overwrite), c1
    s_kernel<<<B_, 160>>>(1, nullptr);
    a_kernel<<<N_, 160>>>(1);
    // iter 1
    s_kernel<<<B_, 160>>>(0, nullptr);
    a_kernel<<<N_, 160>>>(0);
    // iter 2: final v -> d_out (shape [B, C, OUT, 1] == [b][ko] row-major)
    s_kernel<<<B_, 160>>>(0, out);
}

// round 3
// speedup vs baseline: 1.9252x; 1.9252x over previous
#include <cuda_runtime.h>
#include <math.h>

#define B_    256
#define N_    1152
#define C_    10
#define OUT_  16
#define IN_   8
#define KO_   160           // C_*OUT_
#define KO4_  40            // KO_/4 (float4 lanes)
#define G_    16            // reduction-split groups per CTA
#define NTHR  640           // G_*KO4_

// u_hat fp32, layout [n][b][ko]  (189 MB)
__device__ float g_uhat[(size_t)N_ * B_ * KO_];
__device__ float g_bij[N_ * C_];
__device__ float g_c[N_ * C_];
__device__ float g_v[B_ * KO_];

// ---------------------------------------------------------------------------
// Kernel 1: u_hat[n][b][ko] = sum_i W[n,ko,i] * x[b,n,i]
// One CTA per n; warp w owns b=w*32..+31, lane l owns ko=l+32j (j=0..4).
// ---------------------------------------------------------------------------
__global__ __launch_bounds__(256) void uhat_kernel(const float* __restrict__ x,
                                                   const float* __restrict__ W)
{
    __shared__ float WsT[IN_ * KO_];   // [i][ko]
    __shared__ float xs[B_ * IN_];     // [b][i]
    const int n   = blockIdx.x;
    const int tid = threadIdx.x;

    for (int j = tid; j < KO_ * IN_; j += 256) {
        int ko = j >> 3, i = j & 7;
        WsT[i * KO_ + ko] = W[(size_t)n * (KO_ * IN_) + j];
    }
    for (int j = tid; j < B_ * IN_; j += 256) {
        int b = j >> 3, i = j & 7;
        xs[j] = x[(size_t)b * (N_ * IN_) + n * IN_ + i];
    }
    __syncthreads();

    const int w = tid >> 5, l = tid & 31;
    float wr[5][8];
#pragma unroll
    for (int j = 0; j < 5; j++)
#pragma unroll
        for (int i = 0; i < 8; i++)
            wr[j][i] = WsT[i * KO_ + (l + 32 * j)];

    float* up = g_uhat + (size_t)n * (B_ * KO_);
    for (int bb = 0; bb < 32; bb++) {
        const int b = w * 32 + bb;
        float xv[8];
#pragma unroll
        for (int i = 0; i < 8; i++) xv[i] = xs[b * 8 + i];
#pragma unroll
        for (int j = 0; j < 5; j++) {
            float acc = 0.f;
#pragma unroll
            for (int i = 0; i < 8; i++) acc = fmaf(wr[j][i], xv[i], acc);
            up[b * KO_ + l + 32 * j] = acc;
        }
    }
}

// ---------------------------------------------------------------------------
// S-pass: s[b,ko] = sum_n c[n,k] * u_hat[n][b][ko]; v = squash(s).
// One CTA per b; 640 thr = 16 n-groups x 40 float4 lanes (72 n each).
// ---------------------------------------------------------------------------
__global__ __launch_bounds__(NTHR) void s_kernel(int uniform, float* __restrict__ out)
{
    __shared__ float4 spart[G_ * KO4_];
    const int b    = blockIdx.x;
    const int tid  = threadIdx.x;
    const int lane = tid % KO4_;        // float4 lane: ko = 4*lane..4*lane+3
    const int g    = tid / KO4_;        // n-group
    const int k    = lane >> 2;         // capsule (4 float4 lanes per k)

    const float4* up = (const float4*)g_uhat + ((size_t)(g * 72) * B_ + b) * KO4_ + lane;
    const size_t nstride = (size_t)B_ * KO4_;

    float4 acc = make_float4(0.f, 0.f, 0.f, 0.f);
    if (uniform) {
#pragma unroll 8
        for (int nn = 0; nn < 72; nn++) {
            float4 u = up[nn * nstride];
            acc.x += u.x; acc.y += u.y; acc.z += u.z; acc.w += u.w;
        }
        acc.x *= 0.1f; acc.y *= 0.1f; acc.z *= 0.1f; acc.w *= 0.1f;
    } else {
        const float* cp = g_c + (g * 72) * C_ + k;
#pragma unroll 8
        for (int nn = 0; nn < 72; nn++) {
            float  c = __ldg(cp + nn * C_);
            float4 u = up[nn * nstride];
            acc.x = fmaf(c, u.x, acc.x);
            acc.y = fmaf(c, u.y, acc.y);
            acc.z = fmaf(c, u.z, acc.z);
            acc.w = fmaf(c, u.w, acc.w);
        }
    }
    spart[g * KO4_ + lane] = acc;
    __syncthreads();

    if (tid < KO4_) {
        float4 s = spart[tid];
#pragma unroll
        for (int gg = 1; gg < G_; gg++) {
            float4 p = spart[gg * KO4_ + tid];
            s.x += p.x; s.y += p.y; s.z += p.z; s.w += p.w;
        }
        float4 v;
        v.x = s.x * fabsf(s.x) / (1.0f + s.x * s.x);
        v.y = s.y * fabsf(s.y) / (1.0f + s.y * s.y);
        v.z = s.z * fabsf(s.z) / (1.0f + s.z * s.z);
        v.w = s.w * fabsf(s.w) / (1.0f + s.w * s.w);
        float* dst = out ? out : g_v;
        *(float4*)(dst + b * KO_ + 4 * tid) = v;
    }
}

// ---------------------------------------------------------------------------
// A-pass: a[n,k] = (1/B) sum_{b,o} u_hat[n][b][ko] * v[b][ko];
// fused b_ij update + per-n softmax. One CTA per n; 16 b-groups x 40 lanes.
// ---------------------------------------------------------------------------
__global__ __launch_bounds__(NTHR) void a_kernel(int first)
{
    __shared__ float apart[G_][C_];
    __shared__ float sb[C_];
    const int n    = blockIdx.x;
    const int tid  = threadIdx.x;
    const int lane = tid % KO4_;
    const int g    = tid / KO4_;
    const int k    = lane >> 2;

    const float4* up = (const float4*)g_uhat + ((size_t)n * B_ + (size_t)(g * 16)) * KO4_ + lane;
    const float4* vp = (const float4*)g_v + (g * 16) * KO4_ + lane;

    float4 t = make_float4(0.f, 0.f, 0.f, 0.f);
#pragma unroll
    for (int bb = 0; bb < 16; bb++) {
        float4 u = up[bb * KO4_];
        float4 v = __ldg(vp + bb * KO4_);
        t.x = fmaf(u.x, v.x, t.x);
        t.y = fmaf(u.y, v.y, t.y);
        t.z = fmaf(u.z, v.z, t.z);
        t.w = fmaf(u.w, v.w, t.w);
    }
    float ts = (t.x + t.y) + (t.z + t.w);
    // sum over o: 4 float4 lanes per capsule; tid%4 == warp-lane%4, aligned quads
#pragma unroll
    for (int m = 2; m >= 1; m >>= 1)
        ts += __shfl_xor_sync(0xffffffffu, ts, m, 4);

    if ((lane & 3) == 0) apart[g][k] = ts;
    __syncthreads();

    if (tid < C_) {
        float a = 0.f;
#pragma unroll
        for (int gg = 0; gg < G_; gg++) a += apart[gg][tid];
        float bn = a * (1.0f / (float)B_);
        if (!first) bn += g_bij[n * C_ + tid];
        g_bij[n * C_ + tid] = bn;
        sb[tid] = bn;
    }
    __syncthreads();

    if (tid < C_) {
        float mx = -1e30f;
#pragma unroll
        for (int kk = 0; kk < C_; kk++) mx = fmaxf(mx, sb[kk]);
        float sum = 0.f;
#pragma unroll
        for (int kk = 0; kk < C_; kk++) sum += expf(sb[kk] - mx);
        g_c[n * C_ + tid] = expf(sb[tid] - mx) / sum;
    }
}

// ---------------------------------------------------------------------------
extern "C" void kernel_launch(void* const* d_in, const int* in_sizes, int n_in,
                              void* d_out, int out_size)
{
    const float* x = (const float*)d_in[0];
    const float* W = (const float*)d_in[1];
    if (in_sizes[0] == N_ * C_ * OUT_ * IN_) { const float* t = x; x = W; W = t; }
    float* out = (float*)d_out;

    uhat_kernel<<<N_, 256>>>(x, W);

    s_kernel<<<B_, NTHR>>>(1, nullptr);   // iter 0 (uniform c)
    a_kernel<<<N_, NTHR>>>(1);
    s_kernel<<<B_, NTHR>>>(0, nullptr);   // iter 1
    a_kernel<<<N_, NTHR>>>(0);
    s_kernel<<<B_, NTHR>>>(0, out);       // iter 2 -> d_out
}